// round 11
// baseline (speedup 1.0000x reference)
#include <cuda_runtime.h>
#include <cuda_bf16.h>
#include <cstdint>

#define N_NODES 10000
#define DEG 32
#define IN_DIM 256
#define OUT_DIM 256
#define N_HEADS 8
#define HEAD_DIM 32
#define N_EDGES (N_NODES * DEG)

// ---------------- scratch (static device globals; no allocation) -------------
__device__ float g_Q[N_NODES * OUT_DIM];
__device__ float g_K[N_NODES * OUT_DIM];
__device__ float g_V[N_NODES * OUT_DIM];
__device__ int   g_nbr[N_EDGES];
// Pre-split weights: [split(hi/lo)][chunk(4)][264 n-rows][64 k] bf16
// = 2112 uint4 per (s,c). B^T layout: row n holds k-contiguous values.
__device__ uint4 g_WB[2 * 4 * 2112];

// ======================= helpers =============================================
__device__ __forceinline__ uint32_t smem_u32(const void* p) {
    uint32_t a;
    asm("{ .reg .u64 t; cvta.to.shared.u64 t, %1; cvt.u32.u64 %0, t; }" : "=r"(a) : "l"(p));
    return a;
}
#define SWZ(off) ((off) ^ (((off) >> 3) & 0x70))

__device__ __forceinline__ void ldsm_x4(uint32_t* r, uint32_t addr) {
    asm volatile("ldmatrix.sync.aligned.m8n8.x4.shared.b16 {%0,%1,%2,%3}, [%4];"
                 : "=r"(r[0]), "=r"(r[1]), "=r"(r[2]), "=r"(r[3]) : "r"(addr));
}
__device__ __forceinline__ void ldsm_x2(uint32_t* r, uint32_t addr) {
    asm volatile("ldmatrix.sync.aligned.m8n8.x2.shared.b16 {%0,%1}, [%2];"
                 : "=r"(r[0]), "=r"(r[1]) : "r"(addr));
}
__device__ __forceinline__ void mma16816(float* d, const uint32_t* a, const uint32_t* b) {
    asm volatile("mma.sync.aligned.m16n8k16.row.col.f32.bf16.bf16.f32 "
                 "{%0,%1,%2,%3}, {%4,%5,%6,%7}, {%8,%9}, {%0,%1,%2,%3};"
                 : "+f"(d[0]), "+f"(d[1]), "+f"(d[2]), "+f"(d[3])
                 : "r"(a[0]), "r"(a[1]), "r"(a[2]), "r"(a[3]), "r"(b[0]), "r"(b[1]));
}
__device__ __forceinline__ void cp_async16(uint32_t dst, const void* src) {
    asm volatile("cp.async.cg.shared.global [%0], [%1], 16;" :: "r"(dst), "l"(src) : "memory");
}
#define CP_COMMIT() asm volatile("cp.async.commit_group;" ::: "memory")
#define CP_WAIT0()  asm volatile("cp.async.wait_group 0;" ::: "memory")

// ======================= geometry / SMEM layout ==============================
#define TILE_M   128
#define KC       64
#define CHUNKS   4
#define NB_ROWS  264                 // 256 WE1 cols + 8 WE2 cols
#define A_BYTES  (TILE_M * 128)      // 16384 per split (bf16, 128B rows)
#define B_BYTES  (NB_ROWS * 128)     // 33792 per split
#define OFF_A    0                   // [2 buf][2 split] -> 65536
#define OFF_B    65536               // [2 buf][2 split] -> 135168, end 200704
#define OFF_SK   200704              // [128][33] float  = 16896
#define OFF_SC   217600              // [128][9]  float  = 4608
#define OFF_NBR  222208              // [128] int        = 512
#define OFF_SQ   222720              // [8][32] float    = 1024
#define OFF_ATT  223744              // [8][32] float    = 1024
#define SMEM_TOTAL 224768

// ---------------- index normalization (int64 vs int32 robustness) ------------
__global__ void convert_idx_kernel(const int* __restrict__ e32) {
    __shared__ int is64;
    if (threadIdx.x == 0) {
        int z = 1;
        for (int i = 1; i < 128; i += 2)
            if (e32[i] != 0) z = 0;
        is64 = z;
    }
    __syncthreads();
    int i = blockIdx.x * blockDim.x + threadIdx.x;
    if (i < N_EDGES)
        g_nbr[i] = is64 ? e32[2 * i] : e32[i];
}

// ---------------- weight prep: WE1/WE2 -> transposed hi/lo bf16 --------------
__global__ void prep_wb_kernel(const float* __restrict__ WE1, const float* __restrict__ WE2) {
    int idx = blockIdx.x * blockDim.x + threadIdx.x;   // 135168 total
    int s   = idx / 67584;
    int rem = idx % 67584;
    int cc  = rem / 16896;
    int e   = rem % 16896;
    int n   = e >> 6;
    int k   = e & 63;
    int kk  = cc * 64 + k;
    float v = (n < 256) ? WE1[(size_t)kk * 256 + n] : WE2[(size_t)kk * 8 + (n - 256)];
    __nv_bfloat16 hi = __float2bfloat16_rn(v);
    __nv_bfloat16 ov = (s == 0) ? hi : __float2bfloat16_rn(v - __bfloat162float(hi));
    reinterpret_cast<__nv_bfloat16*>(g_WB)[idx] = ov;
}

// ---------------- kernel 1: Q/K/V GEMMs (fp32, exact) ------------------------
__global__ __launch_bounds__(256, 2) void qkv_kernel(
    const float* __restrict__ x,
    const float* __restrict__ WQ, const float* __restrict__ WK,
    const float* __restrict__ WV)
{
    const float* W = (blockIdx.z == 0) ? WQ : (blockIdx.z == 1) ? WK : WV;
    float* out = (blockIdx.z == 0) ? g_Q : (blockIdx.z == 1) ? g_K : g_V;

    __shared__ float As[32][65];
    __shared__ float Bs[32][256];

    const int tid = threadIdx.x;
    const int tx = tid & 15, ty = tid >> 4;
    const int row0 = blockIdx.x * 64;

    float acc[4][16];
#pragma unroll
    for (int r = 0; r < 4; r++)
#pragma unroll
        for (int i = 0; i < 16; i++) acc[r][i] = 0.f;

    for (int k0 = 0; k0 < 256; k0 += 32) {
#pragma unroll
        for (int i = 0; i < 8; i++) {
            int e = i * 256 + tid;
            int r = e >> 5, k = e & 31;
            int gr = row0 + r;
            As[k][r] = (gr < N_NODES) ? x[(size_t)gr * 256 + k0 + k] : 0.f;
        }
#pragma unroll
        for (int i = 0; i < 32; i++)
            Bs[i][tid] = W[(size_t)(k0 + i) * 256 + tid];
        __syncthreads();

#pragma unroll 4
        for (int k = 0; k < 32; k++) {
            float a0 = As[k][ty * 4 + 0], a1 = As[k][ty * 4 + 1];
            float a2 = As[k][ty * 4 + 2], a3 = As[k][ty * 4 + 3];
#pragma unroll
            for (int i = 0; i < 16; i++) {
                float b = Bs[k][tx + 16 * i];
                acc[0][i] += a0 * b; acc[1][i] += a1 * b;
                acc[2][i] += a2 * b; acc[3][i] += a3 * b;
            }
        }
        __syncthreads();
    }

#pragma unroll
    for (int r = 0; r < 4; r++) {
        int gr = row0 + ty * 4 + r;
        if (gr < N_NODES) {
#pragma unroll
            for (int i = 0; i < 16; i++)
                out[(size_t)gr * 256 + tx + 16 * i] = acc[r][i];
        }
    }
}

// ---------------- kernel 2: HMMA E1/E2 + score + softmax + V-agg -------------
__global__ __launch_bounds__(256, 1) void score_fused_kernel(
    const float* __restrict__ ea, const float* __restrict__ bE2v,
    float* __restrict__ out)
{
    extern __shared__ char smem[];
    const uint32_t sb = smem_u32(smem);
    const int tid = threadIdx.x, w = tid >> 5, lane = tid & 31;
    const int g = lane >> 2, q = lane & 3;
    const int row0 = blockIdx.x * TILE_M;

    int* snbr = reinterpret_cast<int*>(smem + OFF_NBR);
    if (tid < 128) snbr[tid] = g_nbr[row0 + tid];

    float acc[33][4];
#pragma unroll
    for (int j = 0; j < 33; j++)
#pragma unroll
        for (int i = 0; i < 4; i++) acc[j][i] = 0.f;

    float4 pf[8];

    // ---- pipeline helpers (lambdas keep code compact) ----
    auto prefetchA = [&](int c) {
#pragma unroll
        for (int i = 0; i < 8; i++) {
            int u = tid + i * 256;           // 2048 float4 total
            int r = u >> 4, gg = u & 15;
            pf[i] = *reinterpret_cast<const float4*>(
                ea + (size_t)(row0 + r) * 256 + c * 64 + gg * 4);
        }
    };
    auto storeA = [&](int buf) {
        char* ah = smem + OFF_A + (size_t)(buf * 2 + 0) * A_BYTES;
        char* al = smem + OFF_A + (size_t)(buf * 2 + 1) * A_BYTES;
#pragma unroll
        for (int i = 0; i < 8; i++) {
            int u = tid + i * 256;
            int r = u >> 4, gg = u & 15;
            float f[4] = {pf[i].x, pf[i].y, pf[i].z, pf[i].w};
            uint32_t hw[2], lw[2];
#pragma unroll
            for (int j = 0; j < 2; j++) {
                __nv_bfloat162 th, tl;
                th.x = __float2bfloat16_rn(f[2 * j]);
                th.y = __float2bfloat16_rn(f[2 * j + 1]);
                tl.x = __float2bfloat16_rn(f[2 * j]     - __bfloat162float(th.x));
                tl.y = __float2bfloat16_rn(f[2 * j + 1] - __bfloat162float(th.y));
                hw[j] = *reinterpret_cast<uint32_t*>(&th);
                lw[j] = *reinterpret_cast<uint32_t*>(&tl);
            }
            uint32_t off = SWZ((uint32_t)(r * 128 + gg * 8));
            *reinterpret_cast<uint2*>(ah + off) = make_uint2(hw[0], hw[1]);
            *reinterpret_cast<uint2*>(al + off) = make_uint2(lw[0], lw[1]);
        }
    };
    auto loadB = [&](int c, int buf) {
        for (int v = tid; v < 4224; v += 256) {
            int s = (v >= 2112) ? 1 : 0;
            int e = v - s * 2112;
            const uint4* src = g_WB + (size_t)(s * 4 + c) * 2112 + e;
            uint32_t dst = sb + OFF_B + (buf * 2 + s) * B_BYTES + SWZ((uint32_t)(e * 16));
            cp_async16(dst, src);
        }
        CP_COMMIT();
    };
    auto mma_chunk = [&](int buf) {
        uint32_t Ah = sb + OFF_A + (buf * 2 + 0) * A_BYTES;
        uint32_t Al = sb + OFF_A + (buf * 2 + 1) * A_BYTES;
        uint32_t Bh = sb + OFF_B + (buf * 2 + 0) * B_BYTES;
        uint32_t Bl = sb + OFF_B + (buf * 2 + 1) * B_BYTES;
        uint32_t a_off = (uint32_t)((16 * w + (lane & 15)) * 128 + (lane >> 4) * 16);
        uint32_t b_off = (uint32_t)((lane & 7) * 128 + ((lane >> 3) & 1) * 16);
#pragma unroll
        for (int ks = 0; ks < 4; ks++) {
            uint32_t ao = SWZ(a_off + ks * 32);
            uint32_t ahf[4], alf[4];
            ldsm_x4(ahf, Ah + ao);
            ldsm_x4(alf, Al + ao);
#pragma unroll
            for (int j = 0; j < 33; j++) {
                uint32_t bo = SWZ((uint32_t)(j * 1024) + b_off + ks * 32);
                uint32_t bhf[2], blf[2];
                ldsm_x2(bhf, Bh + bo);
                ldsm_x2(blf, Bl + bo);
                mma16816(acc[j], ahf, bhf);
                mma16816(acc[j], ahf, blf);
                mma16816(acc[j], alf, bhf);
            }
        }
    };

    // ---- prologue: chunk 0 ----
    prefetchA(0);
    loadB(0, 0);
    storeA(0);
    CP_WAIT0();
    __syncthreads();

    // ---- main loop ----
    for (int c = 0; c < CHUNKS; c++) {
        int b = c & 1;
        if (c < CHUNKS - 1) { prefetchA(c + 1); loadB(c + 1, 1 - b); }
        mma_chunk(b);
        if (c < CHUNKS - 1) {
            storeA(1 - b);
            CP_WAIT0();
            __syncthreads();
        }
    }

    // ---- phase 1: score = frag . (K[nbr] * Q[node]) + E2 + bE2, clipped -----
    float* sk  = reinterpret_cast<float*>(smem + OFF_SK);    // [128][33]
    float* ssc = reinterpret_cast<float*>(smem + OFF_SC);    // [128][9]
    float* sqp = reinterpret_cast<float*>(smem + OFF_SQ) + w * 32;
    const int node = blockIdx.x * 4 + (w >> 1);

    for (int h = 0; h < N_HEADS; h++) {
        // stage this warp's 16 rows of K[nbr], head-local 32 cols (coalesced)
#pragma unroll 4
        for (int j = 0; j < 16; j++) {
            int row = 16 * w + j;
            sk[row * 33 + lane] = g_K[(size_t)snbr[row] * 256 + h * 32 + lane];
        }
        sqp[lane] = g_Q[(size_t)node * 256 + h * 32 + lane];
        __syncwarp();

        float pg = 0.f, pg8 = 0.f;
        const float* skg  = sk + (16 * w + g) * 33;
        const float* skg8 = sk + (16 * w + g + 8) * 33;
#pragma unroll
        for (int j2 = 0; j2 < 4; j2++) {
            int t  = 4 * h + j2;
            int c0 = j2 * 8 + 2 * q;
            float q0 = sqp[c0], q1 = sqp[c0 + 1];
            pg  += acc[t][0] * skg[c0]  * q0 + acc[t][1] * skg[c0 + 1]  * q1;
            pg8 += acc[t][2] * skg8[c0] * q0 + acc[t][3] * skg8[c0 + 1] * q1;
        }
        pg  += __shfl_xor_sync(0xffffffffu, pg, 1);
        pg  += __shfl_xor_sync(0xffffffffu, pg, 2);
        pg8 += __shfl_xor_sync(0xffffffffu, pg8, 1);
        pg8 += __shfl_xor_sync(0xffffffffu, pg8, 2);

        // E2 lives in tile 32, col h: owner lane = g*4 + (h>>1), reg (h&1) / 2+(h&1)
        int srcl = (g << 2) | (h >> 1);
        float e2a = (h & 1) ? acc[32][1] : acc[32][0];
        float e2b = (h & 1) ? acc[32][3] : acc[32][2];
        float e2g  = __shfl_sync(0xffffffffu, e2a, srcl);
        float e2g8 = __shfl_sync(0xffffffffu, e2b, srcl);

        float bh = bE2v[h];
        if (q == 0) {
            float s1 = fminf(fmaxf(pg  + e2g  + bh, -8.f), 8.f);
            float s2 = fminf(fmaxf(pg8 + e2g8 + bh, -8.f), 8.f);
            ssc[(16 * w + g) * 9 + h]     = s1;
            ssc[(16 * w + g + 8) * 9 + h] = s2;
        }
        __syncwarp();
    }
    __syncthreads();

    // ---- phase 2: softmax over deg + V aggregation ---------------------------
    {
        const int nl = w >> 1;                       // node-local 0..3
        const int nd = blockIdx.x * 4 + nl;
        float* att = reinterpret_cast<float*>(smem + OFF_ATT) + w * 32;
#pragma unroll
        for (int hh = 0; hh < 4; hh++) {
            int h = (w & 1) * 4 + hh;
            float s = ssc[(nl * 32 + lane) * 9 + h];
            float m = s;
#pragma unroll
            for (int off = 16; off; off >>= 1)
                m = fmaxf(m, __shfl_xor_sync(0xffffffffu, m, off));
            float ev = __expf(s - m);
            float sum = ev;
#pragma unroll
            for (int off = 16; off; off >>= 1)
                sum += __shfl_xor_sync(0xffffffffu, sum, off);
            att[lane] = ev / sum;
            __syncwarp();

            float a0 = 0.f, a1 = 0.f;
#pragma unroll 8
            for (int dd = 0; dd < 32; dd += 2) {
                a0 += att[dd]     * g_V[(size_t)snbr[nl * 32 + dd]     * 256 + h * 32 + lane];
                a1 += att[dd + 1] * g_V[(size_t)snbr[nl * 32 + dd + 1] * 256 + h * 32 + lane];
            }
            out[(size_t)nd * 256 + h * 32 + lane] = a0 + a1;
            __syncwarp();
        }
    }
}

// ---------------- launch -----------------------------------------------------
extern "C" void kernel_launch(void* const* d_in, const int* in_sizes, int n_in,
                              void* d_out, int out_size)
{
    const float* x   = (const float*)d_in[0];
    const int*   ei  = (const int*)  d_in[1];
    const float* ea  = (const float*)d_in[2];
    const float* WQ  = (const float*)d_in[3];
    const float* WK  = (const float*)d_in[4];
    const float* WV  = (const float*)d_in[5];
    const float* WE1 = (const float*)d_in[6];
    const float* WE2 = (const float*)d_in[7];
    const float* bE2 = (const float*)d_in[8];
    float* out = (float*)d_out;

    cudaFuncSetAttribute(score_fused_kernel,
                         cudaFuncAttributeMaxDynamicSharedMemorySize, SMEM_TOTAL);

    convert_idx_kernel<<<(N_EDGES + 255) / 256, 256>>>(ei);
    prep_wb_kernel<<<528, 256>>>(WE1, WE2);

    dim3 g1((N_NODES + 63) / 64, 1, 3);
    qkv_kernel<<<g1, 256>>>(x, WQ, WK, WV);

    score_fused_kernel<<<N_EDGES / TILE_M, 256, SMEM_TOTAL>>>(ea, bE2, out);
}

// round 14
// speedup vs baseline: 1.5554x; 1.5554x over previous
#include <cuda_runtime.h>
#include <cuda_bf16.h>
#include <cstdint>

#define N_NODES 10000
#define DEG 32
#define IN_DIM 256
#define OUT_DIM 256
#define N_HEADS 8
#define HEAD_DIM 32
#define N_EDGES (N_NODES * DEG)

// ---------------- scratch (static device globals; no allocation) -------------
__device__ float g_Q[N_NODES * OUT_DIM];
__device__ float g_K[N_NODES * OUT_DIM];
__device__ float g_V[N_NODES * OUT_DIM];
__device__ int   g_nbr[N_EDGES];
// Pre-split weights: [split(hi/lo)][chunk(4)][264 n-rows][64 k] bf16
// = 2112 uint4 per (s,c). Row n holds k-contiguous values (B^T).
__device__ uint4 g_WB[2 * 4 * 2112];

// ======================= helpers =============================================
__device__ __forceinline__ uint32_t smem_u32(const void* p) {
    uint32_t a;
    asm("{ .reg .u64 t; cvta.to.shared.u64 t, %1; cvt.u32.u64 %0, t; }" : "=r"(a) : "l"(p));
    return a;
}
#define SWZ(off) ((off) ^ (((off) >> 3) & 0x70))

__device__ __forceinline__ void ldsm_x4(uint32_t* r, uint32_t addr) {
    asm volatile("ldmatrix.sync.aligned.m8n8.x4.shared.b16 {%0,%1,%2,%3}, [%4];"
                 : "=r"(r[0]), "=r"(r[1]), "=r"(r[2]), "=r"(r[3]) : "r"(addr));
}
__device__ __forceinline__ void ldsm_x2(uint32_t* r, uint32_t addr) {
    asm volatile("ldmatrix.sync.aligned.m8n8.x2.shared.b16 {%0,%1}, [%2];"
                 : "=r"(r[0]), "=r"(r[1]) : "r"(addr));
}
__device__ __forceinline__ void mma16816(float* d, const uint32_t* a, const uint32_t* b) {
    asm volatile("mma.sync.aligned.m16n8k16.row.col.f32.bf16.bf16.f32 "
                 "{%0,%1,%2,%3}, {%4,%5,%6,%7}, {%8,%9}, {%0,%1,%2,%3};"
                 : "+f"(d[0]), "+f"(d[1]), "+f"(d[2]), "+f"(d[3])
                 : "r"(a[0]), "r"(a[1]), "r"(a[2]), "r"(a[3]), "r"(b[0]), "r"(b[1]));
}
__device__ __forceinline__ void cp_async16(uint32_t dst, const void* src) {
    asm volatile("cp.async.cg.shared.global [%0], [%1], 16;" :: "r"(dst), "l"(src) : "memory");
}
#define CP_COMMIT() asm volatile("cp.async.commit_group;" ::: "memory")
#define CP_WAIT0()  asm volatile("cp.async.wait_group 0;" ::: "memory")
#define CP_WAIT1()  asm volatile("cp.async.wait_group 1;" ::: "memory")

// ======================= geometry / SMEM layout ==============================
#define TILE_M   128
#define CHUNKS   4            // K chunks of 64
#define NGROUPS  4            // N groups of 64 cols (2 heads each)
#define A_SPLIT_BYTES  16384  // 128 rows x 64 k bf16 (128B rows)
#define B_SPLIT_BYTES  9216   // 72 rows x 128B
#define B_BUF_BYTES    18432  // 2 splits

#define OFF_A    0            // [4 chunk][2 split] * 16384 = 131072
#define OFF_B    131072       // [2 buf] * 18432 = 36864 -> 167936
#define OFF_SK   167936       // [2 wn][128][33] float = 33792 -> 201728
#define OFF_SC   201728       // [128][9] float = 4608 -> 206336
#define OFF_E2   206336       // [128][9] float = 4608 -> 210944
#define OFF_NBR  210944       // [128] int = 512 -> 211456
#define OFF_SQ   211456       // [16 w][32] float = 2048 -> 213504
#define OFF_ATT  213504       // [16 w][32] float = 2048 -> 215552
#define SMEM_TOTAL 215552

// ---------------- index normalization (int64 vs int32 robustness) ------------
__global__ void convert_idx_kernel(const int* __restrict__ e32) {
    __shared__ int is64;
    if (threadIdx.x == 0) {
        int z = 1;
        for (int i = 1; i < 128; i += 2)
            if (e32[i] != 0) z = 0;
        is64 = z;
    }
    __syncthreads();
    int i = blockIdx.x * blockDim.x + threadIdx.x;
    if (i < N_EDGES)
        g_nbr[i] = is64 ? e32[2 * i] : e32[i];
}

// ---------------- weight prep: WE1/WE2 -> transposed hi/lo bf16 --------------
__global__ void prep_wb_kernel(const float* __restrict__ WE1, const float* __restrict__ WE2) {
    int idx = blockIdx.x * blockDim.x + threadIdx.x;   // 135168 total
    int s   = idx / 67584;
    int rem = idx % 67584;
    int cc  = rem / 16896;
    int e   = rem % 16896;
    int n   = e >> 6;
    int k   = e & 63;
    int kk  = cc * 64 + k;
    float v = (n < 256) ? WE1[(size_t)kk * 256 + n] : WE2[(size_t)kk * 8 + (n - 256)];
    __nv_bfloat16 hi = __float2bfloat16_rn(v);
    __nv_bfloat16 ov = (s == 0) ? hi : __float2bfloat16_rn(v - __bfloat162float(hi));
    reinterpret_cast<__nv_bfloat16*>(g_WB)[idx] = ov;
}

// ---------------- kernel 1: Q/K/V GEMMs (fp32, exact) ------------------------
__global__ __launch_bounds__(256, 2) void qkv_kernel(
    const float* __restrict__ x,
    const float* __restrict__ WQ, const float* __restrict__ WK,
    const float* __restrict__ WV)
{
    const float* W = (blockIdx.z == 0) ? WQ : (blockIdx.z == 1) ? WK : WV;
    float* out = (blockIdx.z == 0) ? g_Q : (blockIdx.z == 1) ? g_K : g_V;

    __shared__ float As[32][65];
    __shared__ float Bs[32][256];

    const int tid = threadIdx.x;
    const int tx = tid & 15, ty = tid >> 4;
    const int row0 = blockIdx.x * 64;

    float acc[4][16];
#pragma unroll
    for (int r = 0; r < 4; r++)
#pragma unroll
        for (int i = 0; i < 16; i++) acc[r][i] = 0.f;

    for (int k0 = 0; k0 < 256; k0 += 32) {
#pragma unroll
        for (int i = 0; i < 8; i++) {
            int e = i * 256 + tid;
            int r = e >> 5, k = e & 31;
            int gr = row0 + r;
            As[k][r] = (gr < N_NODES) ? x[(size_t)gr * 256 + k0 + k] : 0.f;
        }
#pragma unroll
        for (int i = 0; i < 32; i++)
            Bs[i][tid] = W[(size_t)(k0 + i) * 256 + tid];
        __syncthreads();

#pragma unroll 4
        for (int k = 0; k < 32; k++) {
            float a0 = As[k][ty * 4 + 0], a1 = As[k][ty * 4 + 1];
            float a2 = As[k][ty * 4 + 2], a3 = As[k][ty * 4 + 3];
#pragma unroll
            for (int i = 0; i < 16; i++) {
                float b = Bs[k][tx + 16 * i];
                acc[0][i] += a0 * b; acc[1][i] += a1 * b;
                acc[2][i] += a2 * b; acc[3][i] += a3 * b;
            }
        }
        __syncthreads();
    }

#pragma unroll
    for (int r = 0; r < 4; r++) {
        int gr = row0 + ty * 4 + r;
        if (gr < N_NODES) {
#pragma unroll
            for (int i = 0; i < 16; i++)
                out[(size_t)gr * 256 + tx + 16 * i] = acc[r][i];
        }
    }
}

// ---------------- kernel 2: HMMA E1/E2 + score + softmax + V-agg -------------
// 512 threads. Warp (wm = w>>1 in 0..7, wn = w&1): 16 M-rows x 32 N-cols.
// A resident in SMEM (all 4 K chunks, hi/lo). N in 4 groups of 64 (2 heads);
// B double-buffered cp.async. Epilogue per group; E2 = extra 8 B rows, grp 3.
__global__ __launch_bounds__(512, 1) void score_fused_kernel(
    const float* __restrict__ ea, const float* __restrict__ bE2v,
    float* __restrict__ out)
{
    extern __shared__ char smem[];
    const uint32_t sb = smem_u32(smem);
    const int tid = threadIdx.x, w = tid >> 5, lane = tid & 31;
    const int wm = w >> 1, wn = w & 1;
    const int g4 = lane >> 2, q = lane & 3;
    const int row0 = blockIdx.x * TILE_M;

    int* snbr = reinterpret_cast<int*>(smem + OFF_NBR);
    if (tid < 128) snbr[tid] = g_nbr[row0 + tid];

    // ---- B loader: group g, chunk c, into buf ----
    auto loadB = [&](int gc, int buf) {
        int g = gc >> 2, c = gc & 3;
        const uint4* base = g_WB;
        for (int v = tid; v < 1152; v += 512) {
            int s   = v / 576;
            int rem = v - s * 576;
            int r   = rem >> 3, u = rem & 7;
            int n   = (r < 64) ? (64 * g + r) : (256 + r - 64);
            const uint4* src = base + (size_t)(s * 4 + c) * 2112 + n * 8 + u;
            uint32_t dst = sb + OFF_B + buf * B_BUF_BYTES + s * B_SPLIT_BYTES
                         + SWZ((uint32_t)(r * 128 + u * 16));
            cp_async16(dst, src);
        }
        CP_COMMIT();
    };

    // ---- prologue: start B(0), fill ALL of A (hi/lo, 4 chunks) --------------
    loadB(0, 0);
    for (int i = tid; i < 8192; i += 512) {            // 8192 float4 = 128KB fp32
        int r  = i >> 6;                               // row 0..127
        int kq = i & 63;                               // float4 idx in row
        float4 v = *reinterpret_cast<const float4*>(
            ea + (size_t)(row0 + r) * 256 + kq * 4);
        int c  = kq >> 4;
        int kk = (kq & 15) * 4;                        // k within chunk
        char* ah = smem + OFF_A + (c * 2 + 0) * A_SPLIT_BYTES;
        char* al = smem + OFF_A + (c * 2 + 1) * A_SPLIT_BYTES;
        float f[4] = {v.x, v.y, v.z, v.w};
        uint32_t hw[2], lw[2];
#pragma unroll
        for (int j = 0; j < 2; j++) {
            __nv_bfloat162 th, tl;
            th.x = __float2bfloat16_rn(f[2 * j]);
            th.y = __float2bfloat16_rn(f[2 * j + 1]);
            tl.x = __float2bfloat16_rn(f[2 * j]     - __bfloat162float(th.x));
            tl.y = __float2bfloat16_rn(f[2 * j + 1] - __bfloat162float(th.y));
            hw[j] = *reinterpret_cast<uint32_t*>(&th);
            lw[j] = *reinterpret_cast<uint32_t*>(&tl);
        }
        uint32_t off = SWZ((uint32_t)(r * 128 + kk * 2));
        *reinterpret_cast<uint2*>(ah + off) = make_uint2(hw[0], hw[1]);
        *reinterpret_cast<uint2*>(al + off) = make_uint2(lw[0], lw[1]);
    }

    float acc[5][4];
#pragma unroll
    for (int j = 0; j < 5; j++)
#pragma unroll
        for (int i = 0; i < 4; i++) acc[j][i] = 0.f;

    float* sk  = reinterpret_cast<float*>(smem + OFF_SK) + wn * (128 * 33);
    float* ssc = reinterpret_cast<float*>(smem + OFF_SC);
    float* se2 = reinterpret_cast<float*>(smem + OFF_E2);
    float* sqp = reinterpret_cast<float*>(smem + OFF_SQ) + w * 32;

    const uint32_t a_off = (uint32_t)((16 * wm + (lane & 15)) * 128 + (lane >> 4) * 16);
    const uint32_t b_off = (uint32_t)((lane & 7) * 128 + ((lane >> 3) & 1) * 16);

    // ---- main loop over (group, chunk) --------------------------------------
    for (int gc = 0; gc < NGROUPS * CHUNKS; gc++) {
        int g = gc >> 2, c = gc & 3, b = gc & 1;
        if (gc < 15) { loadB(gc + 1, 1 - b); CP_WAIT1(); }
        else         { CP_WAIT0(); }
        __syncthreads();

        // MMA on B buf b, A chunk c
        {
            uint32_t Ah = sb + OFF_A + (c * 2 + 0) * A_SPLIT_BYTES;
            uint32_t Al = sb + OFF_A + (c * 2 + 1) * A_SPLIT_BYTES;
            uint32_t Bh = sb + OFF_B + b * B_BUF_BYTES;
            uint32_t Bl = Bh + B_SPLIT_BYTES;
            int ntiles = (g == 3 && wn == 1) ? 5 : 4;
#pragma unroll
            for (int ks = 0; ks < 4; ks++) {
                uint32_t ao = SWZ(a_off + ks * 32);
                uint32_t ahf[4], alf[4];
                ldsm_x4(ahf, Ah + ao);
                ldsm_x4(alf, Al + ao);
#pragma unroll
                for (int j = 0; j < 5; j++) {
                    if (j >= ntiles) break;
                    int brow = (j < 4) ? (32 * wn + 8 * j) : 64;
                    uint32_t bo = SWZ((uint32_t)(brow * 128) + b_off + ks * 32);
                    uint32_t bhf[2], blf[2];
                    ldsm_x2(bhf, Bh + bo);
                    ldsm_x2(blf, Bl + bo);
                    mma16816(acc[j], ahf, bhf);
                    mma16816(acc[j], ahf, blf);
                    mma16816(acc[j], alf, bhf);
                }
            }
        }

        // ---- per-group epilogue after last chunk ----
        if (c == 3) {
            const int h = 2 * g + wn;
            const int node = blockIdx.x * 4 + (wm >> 1);
            // stage K[nbr] head-slice for this warp's 16 rows (coalesced)
#pragma unroll 4
            for (int j = 0; j < 16; j++) {
                int row = 16 * wm + j;
                sk[row * 33 + lane] = g_K[(size_t)snbr[row] * 256 + h * 32 + lane];
            }
            sqp[lane] = g_Q[(size_t)node * 256 + h * 32 + lane];
            __syncwarp();

            float pg = 0.f, pg8 = 0.f;
            const float* skg  = sk + (16 * wm + g4) * 33;
            const float* skg8 = sk + (16 * wm + g4 + 8) * 33;
#pragma unroll
            for (int j2 = 0; j2 < 4; j2++) {
                int c0 = j2 * 8 + 2 * q;
                float q0 = sqp[c0], q1 = sqp[c0 + 1];
                pg  += acc[j2][0] * skg[c0]  * q0 + acc[j2][1] * skg[c0 + 1]  * q1;
                pg8 += acc[j2][2] * skg8[c0] * q0 + acc[j2][3] * skg8[c0 + 1] * q1;
            }
            pg  += __shfl_xor_sync(0xffffffffu, pg, 1);
            pg  += __shfl_xor_sync(0xffffffffu, pg, 2);
            pg8 += __shfl_xor_sync(0xffffffffu, pg8, 1);
            pg8 += __shfl_xor_sync(0xffffffffu, pg8, 2);
            if (q == 0) {
                ssc[(16 * wm + g4) * 9 + h]     = pg;    // raw (E2/bias later)
                ssc[(16 * wm + g4 + 8) * 9 + h] = pg8;
            }
            // E2 tile (group 3, wn=1): lane (g4,q) owns cols 2q,2q+1
            if (g == 3 && wn == 1) {
                se2[(16 * wm + g4) * 9 + 2 * q]         = acc[4][0];
                se2[(16 * wm + g4) * 9 + 2 * q + 1]     = acc[4][1];
                se2[(16 * wm + g4 + 8) * 9 + 2 * q]     = acc[4][2];
                se2[(16 * wm + g4 + 8) * 9 + 2 * q + 1] = acc[4][3];
            }
            // reset accumulators for next group
#pragma unroll
            for (int j = 0; j < 5; j++)
#pragma unroll
                for (int i = 0; i < 4; i++) acc[j][i] = 0.f;
        }
        __syncthreads();
    }

    // ---- cleanup: score = clip(raw + E2 + bE2) ------------------------------
    for (int idx = tid; idx < 1024; idx += 512) {
        int row = idx >> 3, h = idx & 7;
        float s = ssc[row * 9 + h] + se2[row * 9 + h] + bE2v[h];
        ssc[row * 9 + h] = fminf(fmaxf(s, -8.f), 8.f);
    }
    __syncthreads();

    // ---- softmax over deg + V aggregation (32 tasks over 16 warps) ----------
    {
        float* att = reinterpret_cast<float*>(smem + OFF_ATT) + w * 32;
#pragma unroll
        for (int tix = 0; tix < 2; tix++) {
            int t = w + tix * 16;
            int nl = t >> 3, h = t & 7;
            float s = ssc[(nl * 32 + lane) * 9 + h];
            float m = s;
#pragma unroll
            for (int off = 16; off; off >>= 1)
                m = fmaxf(m, __shfl_xor_sync(0xffffffffu, m, off));
            float ev = __expf(s - m);
            float sum = ev;
#pragma unroll
            for (int off = 16; off; off >>= 1)
                sum += __shfl_xor_sync(0xffffffffu, sum, off);
            att[lane] = ev / sum;
            __syncwarp();

            float a0 = 0.f, a1 = 0.f;
#pragma unroll 8
            for (int dd = 0; dd < 32; dd += 2) {
                a0 += att[dd]     * g_V[(size_t)snbr[nl * 32 + dd]     * 256 + h * 32 + lane];
                a1 += att[dd + 1] * g_V[(size_t)snbr[nl * 32 + dd + 1] * 256 + h * 32 + lane];
            }
            out[(size_t)(blockIdx.x * 4 + nl) * 256 + h * 32 + lane] = a0 + a1;
            __syncwarp();
        }
    }
}

// ---------------- launch -----------------------------------------------------
extern "C" void kernel_launch(void* const* d_in, const int* in_sizes, int n_in,
                              void* d_out, int out_size)
{
    const float* x   = (const float*)d_in[0];
    const int*   ei  = (const int*)  d_in[1];
    const float* ea  = (const float*)d_in[2];
    const float* WQ  = (const float*)d_in[3];
    const float* WK  = (const float*)d_in[4];
    const float* WV  = (const float*)d_in[5];
    const float* WE1 = (const float*)d_in[6];
    const float* WE2 = (const float*)d_in[7];
    const float* bE2 = (const float*)d_in[8];
    float* out = (float*)d_out;

    cudaFuncSetAttribute(score_fused_kernel,
                         cudaFuncAttributeMaxDynamicSharedMemorySize, SMEM_TOTAL);

    convert_idx_kernel<<<(N_EDGES + 255) / 256, 256>>>(ei);
    prep_wb_kernel<<<528, 256>>>(WE1, WE2);

    dim3 g1((N_NODES + 63) / 64, 1, 3);
    qkv_kernel<<<g1, 256>>>(x, WQ, WK, WV);

    score_fused_kernel<<<N_EDGES / TILE_M, 512, SMEM_TOTAL>>>(ea, bE2, out);
}

// round 15
// speedup vs baseline: 2.2731x; 1.4614x over previous
#include <cuda_runtime.h>
#include <cuda_bf16.h>
#include <cstdint>

#define N_NODES 10000
#define DEG 32
#define IN_DIM 256
#define OUT_DIM 256
#define N_HEADS 8
#define HEAD_DIM 32
#define N_EDGES (N_NODES * DEG)

// ---------------- scratch (static device globals; no allocation) -------------
__device__ float g_Q[N_NODES * OUT_DIM];
__device__ float g_K[N_NODES * OUT_DIM];
__device__ float g_V[N_NODES * OUT_DIM];
__device__ int   g_nbr[N_EDGES];
// Pre-split E weights: [split(hi/lo)][chunk(4)][264 n-rows][64 k] bf16
__device__ uint4 g_WB[2 * 4 * 2112];
// Pre-split QKV weights: [split][chunk(4)][768 n-rows (Q|K|V)][64 k] bf16
__device__ uint4 g_WQKV[2 * 4 * 768 * 8];

// ======================= helpers =============================================
__device__ __forceinline__ uint32_t smem_u32(const void* p) {
    uint32_t a;
    asm("{ .reg .u64 t; cvta.to.shared.u64 t, %1; cvt.u32.u64 %0, t; }" : "=r"(a) : "l"(p));
    return a;
}
#define SWZ(off) ((off) ^ (((off) >> 3) & 0x70))

__device__ __forceinline__ void ldsm_x4(uint32_t* r, uint32_t addr) {
    asm volatile("ldmatrix.sync.aligned.m8n8.x4.shared.b16 {%0,%1,%2,%3}, [%4];"
                 : "=r"(r[0]), "=r"(r[1]), "=r"(r[2]), "=r"(r[3]) : "r"(addr));
}
__device__ __forceinline__ void ldsm_x2(uint32_t* r, uint32_t addr) {
    asm volatile("ldmatrix.sync.aligned.m8n8.x2.shared.b16 {%0,%1}, [%2];"
                 : "=r"(r[0]), "=r"(r[1]) : "r"(addr));
}
__device__ __forceinline__ void mma16816(float* d, const uint32_t* a, const uint32_t* b) {
    asm volatile("mma.sync.aligned.m16n8k16.row.col.f32.bf16.bf16.f32 "
                 "{%0,%1,%2,%3}, {%4,%5,%6,%7}, {%8,%9}, {%0,%1,%2,%3};"
                 : "+f"(d[0]), "+f"(d[1]), "+f"(d[2]), "+f"(d[3])
                 : "r"(a[0]), "r"(a[1]), "r"(a[2]), "r"(a[3]), "r"(b[0]), "r"(b[1]));
}
__device__ __forceinline__ void cp_async16(uint32_t dst, const void* src) {
    asm volatile("cp.async.cg.shared.global [%0], [%1], 16;" :: "r"(dst), "l"(src) : "memory");
}
#define CP_COMMIT() asm volatile("cp.async.commit_group;" ::: "memory")
#define CP_WAIT0()  asm volatile("cp.async.wait_group 0;" ::: "memory")
#define CP_WAIT1()  asm volatile("cp.async.wait_group 1;" ::: "memory")

// convert float pair -> hi/lo bf16x2 words
__device__ __forceinline__ void split2(float f0, float f1, uint32_t& hw, uint32_t& lw) {
    __nv_bfloat162 th, tl;
    th.x = __float2bfloat16_rn(f0);
    th.y = __float2bfloat16_rn(f1);
    tl.x = __float2bfloat16_rn(f0 - __bfloat162float(th.x));
    tl.y = __float2bfloat16_rn(f1 - __bfloat162float(th.y));
    hw = *reinterpret_cast<uint32_t*>(&th);
    lw = *reinterpret_cast<uint32_t*>(&tl);
}

// ======================= geometry / SMEM layout (score kernel) ===============
#define TILE_M   128
#define CHUNKS   4
#define NGROUPS  4
#define A_SPLIT_BYTES  16384
#define B_SPLIT_BYTES  9216    // 72 rows x 128B
#define B_BUF_BYTES    18432

#define OFF_A    0             // [4 chunk][2 split] * 16384 = 131072
#define OFF_B    131072        // [2 buf] * 18432 -> 167936
#define OFF_SK   167936        // [2 wn][128][33] float -> 201728
#define OFF_SC   201728        // [128][9] float -> 206336
#define OFF_E2   206336        // [128][9] float -> 210944
#define OFF_NBR  210944        // [128] int -> 211456
#define OFF_SQ   211456        // [16 w][32] float -> 213504
#define OFF_ATT  213504        // [16 w][32] float -> 215552
#define SMEM_TOTAL 215552

// qkv kernel smem
#define QOFF_A   0             // 131072
#define QOFF_B   131072        // [2 buf] * 16384 -> 163840
#define QSMEM_TOTAL 163840

// ---------------- index normalization (int64 vs int32 robustness) ------------
__global__ void convert_idx_kernel(const int* __restrict__ e32) {
    __shared__ int is64;
    if (threadIdx.x == 0) {
        int z = 1;
        for (int i = 1; i < 128; i += 2)
            if (e32[i] != 0) z = 0;
        is64 = z;
    }
    __syncthreads();
    int i = blockIdx.x * blockDim.x + threadIdx.x;
    if (i < N_EDGES)
        g_nbr[i] = is64 ? e32[2 * i] : e32[i];
}

// ---------------- weight prep: WE1/WE2 -> transposed hi/lo bf16 --------------
__global__ void prep_wb_kernel(const float* __restrict__ WE1, const float* __restrict__ WE2) {
    int idx = blockIdx.x * blockDim.x + threadIdx.x;   // 135168 total
    int s   = idx / 67584;
    int rem = idx % 67584;
    int cc  = rem / 16896;
    int e   = rem % 16896;
    int n   = e >> 6;
    int k   = e & 63;
    int kk  = cc * 64 + k;
    float v = (n < 256) ? WE1[(size_t)kk * 256 + n] : WE2[(size_t)kk * 8 + (n - 256)];
    __nv_bfloat16 hi = __float2bfloat16_rn(v);
    __nv_bfloat16 ov = (s == 0) ? hi : __float2bfloat16_rn(v - __bfloat162float(hi));
    reinterpret_cast<__nv_bfloat16*>(g_WB)[idx] = ov;
}

// ---------------- weight prep: WQ|WK|WV -> transposed hi/lo bf16 -------------
__global__ void prep_wqkv_kernel(const float* __restrict__ WQ,
                                 const float* __restrict__ WK,
                                 const float* __restrict__ WV) {
    int idx = blockIdx.x * blockDim.x + threadIdx.x;   // 393216 total
    int s   = idx / 196608;
    int rem = idx % 196608;
    int cc  = rem / 49152;
    int e   = rem % 49152;
    int n   = e >> 6;                                  // 0..767
    int k   = e & 63;
    int kk  = cc * 64 + k;
    float v = (n < 256) ? WQ[(size_t)kk * 256 + n]
            : (n < 512) ? WK[(size_t)kk * 256 + (n - 256)]
                        : WV[(size_t)kk * 256 + (n - 512)];
    __nv_bfloat16 hi = __float2bfloat16_rn(v);
    __nv_bfloat16 ov = (s == 0) ? hi : __float2bfloat16_rn(v - __bfloat162float(hi));
    reinterpret_cast<__nv_bfloat16*>(g_WQKV)[idx] = ov;
}

// ---------------- kernel 1: Q/K/V via HMMA hi/lo split -----------------------
// grid 79, 512 threads. A = x tile (128 rows) resident hi/lo. 12 N-groups
// (Q:0-3, K:4-7, V:8-11) x 4 K-chunks, B double-buffered cp.async.
__global__ __launch_bounds__(512, 1) void qkv_mma_kernel(const float* __restrict__ x)
{
    extern __shared__ char smem[];
    const uint32_t sb = smem_u32(smem);
    const int tid = threadIdx.x, w = tid >> 5, lane = tid & 31;
    const int wm = w >> 1, wn = w & 1;
    const int g4 = lane >> 2, q = lane & 3;
    const int row0 = blockIdx.x * TILE_M;

    auto loadWB = [&](int gc, int buf) {
        int g = gc / 4, c = gc & 3;
        for (int v = tid; v < 1024; v += 512) {
            int s = v >> 9, rem = v & 511;
            int r = rem >> 3, u = rem & 7;
            const uint4* src = g_WQKV + ((size_t)(s * 4 + c) * 768 + 64 * g + r) * 8 + u;
            uint32_t dst = sb + QOFF_B + buf * 16384 + s * 8192
                         + SWZ((uint32_t)(r * 128 + u * 16));
            cp_async16(dst, src);
        }
        CP_COMMIT();
    };

    loadWB(0, 0);
    // fill A (x rows, clamped) hi/lo
#pragma unroll 2
    for (int i = tid; i < 8192; i += 512) {
        int r  = i >> 6, kq = i & 63;
        int gr = row0 + r;
        if (gr >= N_NODES) gr = N_NODES - 1;
        float4 v = *reinterpret_cast<const float4*>(x + (size_t)gr * 256 + kq * 4);
        int c  = kq >> 4, kk = (kq & 15) * 4;
        char* ah = smem + QOFF_A + (c * 2 + 0) * A_SPLIT_BYTES;
        char* al = smem + QOFF_A + (c * 2 + 1) * A_SPLIT_BYTES;
        uint32_t hw0, lw0, hw1, lw1;
        split2(v.x, v.y, hw0, lw0);
        split2(v.z, v.w, hw1, lw1);
        uint32_t off = SWZ((uint32_t)(r * 128 + kk * 2));
        *reinterpret_cast<uint2*>(ah + off) = make_uint2(hw0, hw1);
        *reinterpret_cast<uint2*>(al + off) = make_uint2(lw0, lw1);
    }

    float acc[4][4];
#pragma unroll
    for (int j = 0; j < 4; j++)
#pragma unroll
        for (int i = 0; i < 4; i++) acc[j][i] = 0.f;

    const uint32_t a_off  = (uint32_t)((16 * wm + (lane & 15)) * 128 + (lane >> 4) * 16);
    const uint32_t bp_off = (uint32_t)(((lane & 7) + ((lane & 16) >> 1)) * 128
                                       + ((lane >> 3) & 1) * 16);

    for (int gc = 0; gc < 48; gc++) {
        int g = gc >> 2, c = gc & 3, b = gc & 1;
        if (gc < 47) { loadWB(gc + 1, 1 - b); CP_WAIT1(); }
        else         { CP_WAIT0(); }
        __syncthreads();

        uint32_t Ah = sb + QOFF_A + (c * 2 + 0) * A_SPLIT_BYTES;
        uint32_t Al = sb + QOFF_A + (c * 2 + 1) * A_SPLIT_BYTES;
        uint32_t Bh = sb + QOFF_B + b * 16384;
        uint32_t Bl = Bh + 8192;
#pragma unroll
        for (int ks = 0; ks < 4; ks++) {
            uint32_t ao = SWZ(a_off + ks * 32);
            uint32_t ahf[4], alf[4];
            ldsm_x4(ahf, Ah + ao);
            ldsm_x4(alf, Al + ao);
#pragma unroll
            for (int jp = 0; jp < 2; jp++) {
                uint32_t bo = SWZ((uint32_t)((32 * wn + 16 * jp) * 128) + bp_off + ks * 32);
                uint32_t bh4[4], bl4[4];
                ldsm_x4(bh4, Bh + bo);
                ldsm_x4(bl4, Bl + bo);
                mma16816(acc[2 * jp],     ahf, &bh4[0]);
                mma16816(acc[2 * jp],     ahf, &bl4[0]);
                mma16816(acc[2 * jp],     alf, &bh4[0]);
                mma16816(acc[2 * jp + 1], ahf, &bh4[2]);
                mma16816(acc[2 * jp + 1], ahf, &bl4[2]);
                mma16816(acc[2 * jp + 1], alf, &bh4[2]);
            }
        }

        if (c == 3) {
            int m = g >> 2;
            float* dst = (m == 0) ? g_Q : (m == 1) ? g_K : g_V;
            int colbase = (g & 3) * 64 + wn * 32;
            int rlo = row0 + 16 * wm + g4;
            int rhi = rlo + 8;
#pragma unroll
            for (int j = 0; j < 4; j++) {
                int col = colbase + j * 8 + 2 * q;
                if (rlo < N_NODES)
                    *reinterpret_cast<float2*>(&dst[(size_t)rlo * 256 + col]) =
                        make_float2(acc[j][0], acc[j][1]);
                if (rhi < N_NODES)
                    *reinterpret_cast<float2*>(&dst[(size_t)rhi * 256 + col]) =
                        make_float2(acc[j][2], acc[j][3]);
            }
#pragma unroll
            for (int j = 0; j < 4; j++)
#pragma unroll
                for (int i = 0; i < 4; i++) acc[j][i] = 0.f;
        }
        __syncthreads();
    }
}

// ---------------- kernel 2: HMMA E1/E2 + score + softmax + V-agg -------------
__global__ __launch_bounds__(512, 1) void score_fused_kernel(
    const float* __restrict__ ea, const float* __restrict__ bE2v,
    float* __restrict__ out)
{
    extern __shared__ char smem[];
    const uint32_t sb = smem_u32(smem);
    const int tid = threadIdx.x, w = tid >> 5, lane = tid & 31;
    const int wm = w >> 1, wn = w & 1;
    const int g4 = lane >> 2, q = lane & 3;
    const int row0 = blockIdx.x * TILE_M;

    int* snbr = reinterpret_cast<int*>(smem + OFF_NBR);
    if (tid < 128) snbr[tid] = g_nbr[row0 + tid];

    auto loadB = [&](int gc, int buf) {
        int g = gc >> 2, c = gc & 3;
        for (int v = tid; v < 1152; v += 512) {
            int s   = v / 576;
            int rem = v - s * 576;
            int r   = rem >> 3, u = rem & 7;
            int n   = (r < 64) ? (64 * g + r) : (256 + r - 64);
            const uint4* src = g_WB + (size_t)(s * 4 + c) * 2112 + n * 8 + u;
            uint32_t dst = sb + OFF_B + buf * B_BUF_BYTES + s * B_SPLIT_BYTES
                         + SWZ((uint32_t)(r * 128 + u * 16));
            cp_async16(dst, src);
        }
        CP_COMMIT();
    };

    loadB(0, 0);
#pragma unroll 2
    for (int i = tid; i < 8192; i += 512) {
        int r  = i >> 6, kq = i & 63;
        float4 v = *reinterpret_cast<const float4*>(
            ea + (size_t)(row0 + r) * 256 + kq * 4);
        int c  = kq >> 4, kk = (kq & 15) * 4;
        char* ah = smem + OFF_A + (c * 2 + 0) * A_SPLIT_BYTES;
        char* al = smem + OFF_A + (c * 2 + 1) * A_SPLIT_BYTES;
        uint32_t hw0, lw0, hw1, lw1;
        split2(v.x, v.y, hw0, lw0);
        split2(v.z, v.w, hw1, lw1);
        uint32_t off = SWZ((uint32_t)(r * 128 + kk * 2));
        *reinterpret_cast<uint2*>(ah + off) = make_uint2(hw0, hw1);
        *reinterpret_cast<uint2*>(al + off) = make_uint2(lw0, lw1);
    }

    float acc[5][4];
#pragma unroll
    for (int j = 0; j < 5; j++)
#pragma unroll
        for (int i = 0; i < 4; i++) acc[j][i] = 0.f;

    float kpf[16];    // K[nbr] prefetch (c==0 -> used at c==3)
    float qpf = 0.f;

    float* sk  = reinterpret_cast<float*>(smem + OFF_SK) + wn * (128 * 33);
    float* ssc = reinterpret_cast<float*>(smem + OFF_SC);
    float* se2 = reinterpret_cast<float*>(smem + OFF_E2);
    float* sqp = reinterpret_cast<float*>(smem + OFF_SQ) + w * 32;
    const int node = blockIdx.x * 4 + (wm >> 1);

    const uint32_t a_off  = (uint32_t)((16 * wm + (lane & 15)) * 128 + (lane >> 4) * 16);
    const uint32_t bp_off = (uint32_t)(((lane & 7) + ((lane & 16) >> 1)) * 128
                                       + ((lane >> 3) & 1) * 16);
    const uint32_t b_off  = (uint32_t)((lane & 7) * 128 + ((lane >> 3) & 1) * 16);

    for (int gc = 0; gc < NGROUPS * CHUNKS; gc++) {
        int g = gc >> 2, c = gc & 3, b = gc & 1;
        if (gc < 15) { loadB(gc + 1, 1 - b); CP_WAIT1(); }
        else         { CP_WAIT0(); }
        __syncthreads();

        // prefetch this group's K/Q gathers; latency covered by 4 MMA phases
        if (c == 0) {
            int h = 2 * g + wn;
#pragma unroll
            for (int j = 0; j < 16; j++)
                kpf[j] = g_K[(size_t)snbr[16 * wm + j] * 256 + h * 32 + lane];
            qpf = g_Q[(size_t)node * 256 + (2 * g + wn) * 32 + lane];
        }

        // MMA on B buf b, A chunk c
        {
            uint32_t Ah = sb + OFF_A + (c * 2 + 0) * A_SPLIT_BYTES;
            uint32_t Al = sb + OFF_A + (c * 2 + 1) * A_SPLIT_BYTES;
            uint32_t Bh = sb + OFF_B + b * B_BUF_BYTES;
            uint32_t Bl = Bh + B_SPLIT_BYTES;
            bool do_e2 = (g == 3 && wn == 1);
#pragma unroll
            for (int ks = 0; ks < 4; ks++) {
                uint32_t ao = SWZ(a_off + ks * 32);
                uint32_t ahf[4], alf[4];
                ldsm_x4(ahf, Ah + ao);
                ldsm_x4(alf, Al + ao);
#pragma unroll
                for (int jp = 0; jp < 2; jp++) {
                    uint32_t bo = SWZ((uint32_t)((32 * wn + 16 * jp) * 128) + bp_off + ks * 32);
                    uint32_t bh4[4], bl4[4];
                    ldsm_x4(bh4, Bh + bo);
                    ldsm_x4(bl4, Bl + bo);
                    mma16816(acc[2 * jp],     ahf, &bh4[0]);
                    mma16816(acc[2 * jp],     ahf, &bl4[0]);
                    mma16816(acc[2 * jp],     alf, &bh4[0]);
                    mma16816(acc[2 * jp + 1], ahf, &bh4[2]);
                    mma16816(acc[2 * jp + 1], ahf, &bl4[2]);
                    mma16816(acc[2 * jp + 1], alf, &bh4[2]);
                }
                if (do_e2) {
                    uint32_t bo = SWZ((uint32_t)(64 * 128) + b_off + ks * 32);
                    uint32_t bhf[2], blf[2];
                    ldsm_x2(bhf, Bh + bo);
                    ldsm_x2(blf, Bl + bo);
                    mma16816(acc[4], ahf, bhf);
                    mma16816(acc[4], ahf, blf);
                    mma16816(acc[4], alf, bhf);
                }
            }
        }

        // ---- per-group epilogue after last chunk ----
        if (c == 3) {
            const int h = 2 * g + wn;
#pragma unroll
            for (int j = 0; j < 16; j++)
                sk[(16 * wm + j) * 33 + lane] = kpf[j];
            sqp[lane] = qpf;
            __syncwarp();

            float pg = 0.f, pg8 = 0.f;
            const float* skg  = sk + (16 * wm + g4) * 33;
            const float* skg8 = sk + (16 * wm + g4 + 8) * 33;
#pragma unroll
            for (int j2 = 0; j2 < 4; j2++) {
                int c0 = j2 * 8 + 2 * q;
                float q0 = sqp[c0], q1 = sqp[c0 + 1];
                pg  += acc[j2][0] * skg[c0]  * q0 + acc[j2][1] * skg[c0 + 1]  * q1;
                pg8 += acc[j2][2] * skg8[c0] * q0 + acc[j2][3] * skg8[c0 + 1] * q1;
            }
            pg  += __shfl_xor_sync(0xffffffffu, pg, 1);
            pg  += __shfl_xor_sync(0xffffffffu, pg, 2);
            pg8 += __shfl_xor_sync(0xffffffffu, pg8, 1);
            pg8 += __shfl_xor_sync(0xffffffffu, pg8, 2);
            if (q == 0) {
                ssc[(16 * wm + g4) * 9 + h]     = pg;
                ssc[(16 * wm + g4 + 8) * 9 + h] = pg8;
            }
            if (g == 3 && wn == 1) {
                se2[(16 * wm + g4) * 9 + 2 * q]         = acc[4][0];
                se2[(16 * wm + g4) * 9 + 2 * q + 1]     = acc[4][1];
                se2[(16 * wm + g4 + 8) * 9 + 2 * q]     = acc[4][2];
                se2[(16 * wm + g4 + 8) * 9 + 2 * q + 1] = acc[4][3];
            }
#pragma unroll
            for (int j = 0; j < 5; j++)
#pragma unroll
                for (int i = 0; i < 4; i++) acc[j][i] = 0.f;
        }
        __syncthreads();
    }

    // ---- cleanup: score = clip(raw + E2 + bE2) ------------------------------
    for (int idx = tid; idx < 1024; idx += 512) {
        int row = idx >> 3, h = idx & 7;
        float s = ssc[row * 9 + h] + se2[row * 9 + h] + bE2v[h];
        ssc[row * 9 + h] = fminf(fmaxf(s, -8.f), 8.f);
    }
    __syncthreads();

    // ---- softmax over deg + V aggregation (32 tasks over 16 warps) ----------
    {
        float* att = reinterpret_cast<float*>(smem + OFF_ATT) + w * 32;
#pragma unroll
        for (int tix = 0; tix < 2; tix++) {
            int t = w + tix * 16;
            int nl = t >> 3, h = t & 7;
            float s = ssc[(nl * 32 + lane) * 9 + h];
            float m = s;
#pragma unroll
            for (int off = 16; off; off >>= 1)
                m = fmaxf(m, __shfl_xor_sync(0xffffffffu, m, off));
            float ev = __expf(s - m);
            float sum = ev;
#pragma unroll
            for (int off = 16; off; off >>= 1)
                sum += __shfl_xor_sync(0xffffffffu, sum, off);
            att[lane] = ev / sum;
            __syncwarp();

            float a0 = 0.f, a1 = 0.f;
#pragma unroll 8
            for (int dd = 0; dd < 32; dd += 2) {
                a0 += att[dd]     * g_V[(size_t)snbr[nl * 32 + dd]     * 256 + h * 32 + lane];
                a1 += att[dd + 1] * g_V[(size_t)snbr[nl * 32 + dd + 1] * 256 + h * 32 + lane];
            }
            out[(size_t)(blockIdx.x * 4 + nl) * 256 + h * 32 + lane] = a0 + a1;
            __syncwarp();
        }
    }
}

// ---------------- launch -----------------------------------------------------
extern "C" void kernel_launch(void* const* d_in, const int* in_sizes, int n_in,
                              void* d_out, int out_size)
{
    const float* x   = (const float*)d_in[0];
    const int*   ei  = (const int*)  d_in[1];
    const float* ea  = (const float*)d_in[2];
    const float* WQ  = (const float*)d_in[3];
    const float* WK  = (const float*)d_in[4];
    const float* WV  = (const float*)d_in[5];
    const float* WE1 = (const float*)d_in[6];
    const float* WE2 = (const float*)d_in[7];
    const float* bE2 = (const float*)d_in[8];
    float* out = (float*)d_out;

    cudaFuncSetAttribute(score_fused_kernel,
                         cudaFuncAttributeMaxDynamicSharedMemorySize, SMEM_TOTAL);
    cudaFuncSetAttribute(qkv_mma_kernel,
                         cudaFuncAttributeMaxDynamicSharedMemorySize, QSMEM_TOTAL);

    convert_idx_kernel<<<(N_EDGES + 255) / 256, 256>>>(ei);
    prep_wb_kernel<<<528, 256>>>(WE1, WE2);
    prep_wqkv_kernel<<<1536, 256>>>(WQ, WK, WV);

    qkv_mma_kernel<<<(N_NODES + TILE_M - 1) / TILE_M, 512, QSMEM_TOTAL>>>(x);

    score_fused_kernel<<<N_EDGES / TILE_M, 512, SMEM_TOTAL>>>(ea, bE2, out);
}

// round 17
// speedup vs baseline: 2.4686x; 1.0860x over previous
#include <cuda_runtime.h>
#include <cuda_bf16.h>
#include <cstdint>

#define N_NODES 10000
#define DEG 32
#define IN_DIM 256
#define OUT_DIM 256
#define N_HEADS 8
#define HEAD_DIM 32
#define N_EDGES (N_NODES * DEG)

// ---------------- scratch (static device globals; no allocation) -------------
__device__ float g_Q[N_NODES * OUT_DIM];
__device__ float g_K[N_NODES * OUT_DIM];
__device__ float g_V[N_NODES * OUT_DIM];
__device__ int   g_nbr[N_EDGES];
// Pre-split E weights: [split(hi/lo)][chunk(4)][264 n-rows][64 k] bf16
__device__ uint4 g_WB[2 * 4 * 2112];
// Pre-split QKV weights: [split][chunk(4)][768 n-rows (Q|K|V)][64 k] bf16
__device__ uint4 g_WQKV[2 * 4 * 768 * 8];

// ======================= helpers =============================================
__device__ __forceinline__ uint32_t smem_u32(const void* p) {
    uint32_t a;
    asm("{ .reg .u64 t; cvta.to.shared.u64 t, %1; cvt.u32.u64 %0, t; }" : "=r"(a) : "l"(p));
    return a;
}
#define SWZ(off) ((off) ^ (((off) >> 3) & 0x70))

__device__ __forceinline__ void ldsm_x4(uint32_t* r, uint32_t addr) {
    asm volatile("ldmatrix.sync.aligned.m8n8.x4.shared.b16 {%0,%1,%2,%3}, [%4];"
                 : "=r"(r[0]), "=r"(r[1]), "=r"(r[2]), "=r"(r[3]) : "r"(addr));
}
__device__ __forceinline__ void ldsm_x2(uint32_t* r, uint32_t addr) {
    asm volatile("ldmatrix.sync.aligned.m8n8.x2.shared.b16 {%0,%1}, [%2];"
                 : "=r"(r[0]), "=r"(r[1]) : "r"(addr));
}
__device__ __forceinline__ void mma16816(float* d, const uint32_t* a, const uint32_t* b) {
    asm volatile("mma.sync.aligned.m16n8k16.row.col.f32.bf16.bf16.f32 "
                 "{%0,%1,%2,%3}, {%4,%5,%6,%7}, {%8,%9}, {%0,%1,%2,%3};"
                 : "+f"(d[0]), "+f"(d[1]), "+f"(d[2]), "+f"(d[3])
                 : "r"(a[0]), "r"(a[1]), "r"(a[2]), "r"(a[3]), "r"(b[0]), "r"(b[1]));
}
__device__ __forceinline__ void cp_async16(uint32_t dst, const void* src) {
    asm volatile("cp.async.cg.shared.global [%0], [%1], 16;" :: "r"(dst), "l"(src) : "memory");
}
#define CP_COMMIT() asm volatile("cp.async.commit_group;" ::: "memory")
#define CP_WAIT0()  asm volatile("cp.async.wait_group 0;" ::: "memory")
#define CP_WAIT1()  asm volatile("cp.async.wait_group 1;" ::: "memory")

// convert float pair -> hi/lo bf16x2 words
__device__ __forceinline__ void split2(float f0, float f1, uint32_t& hw, uint32_t& lw) {
    __nv_bfloat162 th, tl;
    th.x = __float2bfloat16_rn(f0);
    th.y = __float2bfloat16_rn(f1);
    tl.x = __float2bfloat16_rn(f0 - __bfloat162float(th.x));
    tl.y = __float2bfloat16_rn(f1 - __bfloat162float(th.y));
    hw = *reinterpret_cast<uint32_t*>(&th);
    lw = *reinterpret_cast<uint32_t*>(&tl);
}

// ======================= geometry / SMEM layout (score kernel) ===============
#define TILE_M   128
#define N_TILES  (N_EDGES / TILE_M)   // 2500
#define GRID_P   148
#define A_SPLIT_BYTES  16384
#define B_SPLIT_BYTES  9216    // 72 rows x 128B
#define B_BUF_BYTES    18432

#define OFF_A    0             // [4 chunk][2 split] * 16384 = 131072
#define OFF_B    131072        // [2 ring] * 18432 -> 167936
#define OFF_SK   167936        // [2 wn][128][33] float -> 201728
#define OFF_SC   201728        // [128][9] float -> 206336
#define OFF_E2   206336        // [128][9] float -> 210944
#define OFF_NBR  210944        // [2 parity][128] int -> 211968
#define OFF_SQ   211968        // [16 w][32] float -> 214016
#define OFF_ATT  214016        // [16 w][32] float -> 216064
#define SMEM_TOTAL 216064

// qkv kernel smem (TILE_M=64, 256 threads, 2 CTAs/SM)
#define QTILE_M  64
#define QA_SPLIT 8192
#define QOFF_A   0             // [4][2]*8192 = 65536
#define QOFF_B   65536         // [2 buf]*16384 -> 98304
#define QSMEM_TOTAL 98304

// ---------------- index normalization (int64 vs int32 robustness) ------------
__global__ void convert_idx_kernel(const int* __restrict__ e32) {
    __shared__ int is64;
    if (threadIdx.x == 0) {
        int z = 1;
        for (int i = 1; i < 128; i += 2)
            if (e32[i] != 0) z = 0;
        is64 = z;
    }
    __syncthreads();
    int i = blockIdx.x * blockDim.x + threadIdx.x;
    if (i < N_EDGES)
        g_nbr[i] = is64 ? e32[2 * i] : e32[i];
}

// ---------------- weight prep: WE1/WE2 -> transposed hi/lo bf16 --------------
__global__ void prep_wb_kernel(const float* __restrict__ WE1, const float* __restrict__ WE2) {
    int idx = blockIdx.x * blockDim.x + threadIdx.x;   // 135168 total
    int s   = idx / 67584;
    int rem = idx % 67584;
    int cc  = rem / 16896;
    int e   = rem % 16896;
    int n   = e >> 6;
    int k   = e & 63;
    int kk  = cc * 64 + k;
    float v = (n < 256) ? WE1[(size_t)kk * 256 + n] : WE2[(size_t)kk * 8 + (n - 256)];
    __nv_bfloat16 hi = __float2bfloat16_rn(v);
    __nv_bfloat16 ov = (s == 0) ? hi : __float2bfloat16_rn(v - __bfloat162float(hi));
    reinterpret_cast<__nv_bfloat16*>(g_WB)[idx] = ov;
}

// ---------------- weight prep: WQ|WK|WV -> transposed hi/lo bf16 -------------
__global__ void prep_wqkv_kernel(const float* __restrict__ WQ,
                                 const float* __restrict__ WK,
                                 const float* __restrict__ WV) {
    int idx = blockIdx.x * blockDim.x + threadIdx.x;   // 393216 total
    int s   = idx / 196608;
    int rem = idx % 196608;
    int cc  = rem / 49152;
    int e   = rem % 49152;
    int n   = e >> 6;                                  // 0..767
    int k   = e & 63;
    int kk  = cc * 64 + k;
    float v = (n < 256) ? WQ[(size_t)kk * 256 + n]
            : (n < 512) ? WK[(size_t)kk * 256 + (n - 256)]
                        : WV[(size_t)kk * 256 + (n - 512)];
    __nv_bfloat16 hi = __float2bfloat16_rn(v);
    __nv_bfloat16 ov = (s == 0) ? hi : __float2bfloat16_rn(v - __bfloat162float(hi));
    reinterpret_cast<__nv_bfloat16*>(g_WQKV)[idx] = ov;
}

// ---------------- kernel 1: Q/K/V via HMMA hi/lo split -----------------------
// TILE_M=64, 256 threads, 2 CTAs/SM, grid 157. Warps (wm 0..3, wn 0..1):
// each covers 16 M-rows x 32 N-cols. 12 N-groups x 4 K-chunks.
__global__ __launch_bounds__(256, 2) void qkv_mma_kernel(const float* __restrict__ x)
{
    extern __shared__ char smem[];
    const uint32_t sb = smem_u32(smem);
    const int tid = threadIdx.x, w = tid >> 5, lane = tid & 31;
    const int wm = w >> 1, wn = w & 1;
    const int g4 = lane >> 2, q = lane & 3;
    const int row0 = blockIdx.x * QTILE_M;

    auto loadWB = [&](int gc, int buf) {
        int g = gc / 4, c = gc & 3;
        for (int v = tid; v < 1024; v += 256) {
            int s = v >> 9, rem = v & 511;
            int r = rem >> 3, u = rem & 7;
            const uint4* src = g_WQKV + ((size_t)(s * 4 + c) * 768 + 64 * g + r) * 8 + u;
            uint32_t dst = sb + QOFF_B + buf * 16384 + s * 8192
                         + SWZ((uint32_t)(r * 128 + u * 16));
            cp_async16(dst, src);
        }
        CP_COMMIT();
    };

    loadWB(0, 0);
    // fill A (x rows, clamped) hi/lo
#pragma unroll 2
    for (int i = tid; i < 4096; i += 256) {
        int r  = i >> 6, kq = i & 63;
        int gr = row0 + r;
        if (gr >= N_NODES) gr = N_NODES - 1;
        float4 v = *reinterpret_cast<const float4*>(x + (size_t)gr * 256 + kq * 4);
        int c  = kq >> 4, kk = (kq & 15) * 4;
        char* ah = smem + QOFF_A + (c * 2 + 0) * QA_SPLIT;
        char* al = smem + QOFF_A + (c * 2 + 1) * QA_SPLIT;
        uint32_t hw0, lw0, hw1, lw1;
        split2(v.x, v.y, hw0, lw0);
        split2(v.z, v.w, hw1, lw1);
        uint32_t off = SWZ((uint32_t)(r * 128 + kk * 2));
        *reinterpret_cast<uint2*>(ah + off) = make_uint2(hw0, hw1);
        *reinterpret_cast<uint2*>(al + off) = make_uint2(lw0, lw1);
    }

    float acc[4][4];
#pragma unroll
    for (int j = 0; j < 4; j++)
#pragma unroll
        for (int i = 0; i < 4; i++) acc[j][i] = 0.f;

    const uint32_t a_off  = (uint32_t)((16 * wm + (lane & 15)) * 128 + (lane >> 4) * 16);
    const uint32_t bp_off = (uint32_t)(((lane & 7) + ((lane & 16) >> 1)) * 128
                                       + ((lane >> 3) & 1) * 16);

    for (int gc = 0; gc < 48; gc++) {
        int g = gc >> 2, c = gc & 3, b = gc & 1;
        if (gc < 47) { loadWB(gc + 1, 1 - b); CP_WAIT1(); }
        else         { CP_WAIT0(); }
        __syncthreads();

        uint32_t Ah = sb + QOFF_A + (c * 2 + 0) * QA_SPLIT;
        uint32_t Al = sb + QOFF_A + (c * 2 + 1) * QA_SPLIT;
        uint32_t Bh = sb + QOFF_B + b * 16384;
        uint32_t Bl = Bh + 8192;
#pragma unroll
        for (int ks = 0; ks < 4; ks++) {
            uint32_t ao = SWZ(a_off + ks * 32);
            uint32_t ahf[4], alf[4];
            ldsm_x4(ahf, Ah + ao);
            ldsm_x4(alf, Al + ao);
#pragma unroll
            for (int jp = 0; jp < 2; jp++) {
                uint32_t bo = SWZ((uint32_t)((32 * wn + 16 * jp) * 128) + bp_off + ks * 32);
                uint32_t bh4[4], bl4[4];
                ldsm_x4(bh4, Bh + bo);
                ldsm_x4(bl4, Bl + bo);
                mma16816(acc[2 * jp],     ahf, &bh4[0]);
                mma16816(acc[2 * jp],     ahf, &bl4[0]);
                mma16816(acc[2 * jp],     alf, &bh4[0]);
                mma16816(acc[2 * jp + 1], ahf, &bh4[2]);
                mma16816(acc[2 * jp + 1], ahf, &bl4[2]);
                mma16816(acc[2 * jp + 1], alf, &bh4[2]);
            }
        }

        if (c == 3) {
            int m = g >> 2;
            float* dst = (m == 0) ? g_Q : (m == 1) ? g_K : g_V;
            int colbase = (g & 3) * 64 + wn * 32;
            int rlo = row0 + 16 * wm + g4;
            int rhi = rlo + 8;
#pragma unroll
            for (int j = 0; j < 4; j++) {
                int col = colbase + j * 8 + 2 * q;
                if (rlo < N_NODES)
                    *reinterpret_cast<float2*>(&dst[(size_t)rlo * 256 + col]) =
                        make_float2(acc[j][0], acc[j][1]);
                if (rhi < N_NODES)
                    *reinterpret_cast<float2*>(&dst[(size_t)rhi * 256 + col]) =
                        make_float2(acc[j][2], acc[j][3]);
            }
#pragma unroll
            for (int j = 0; j < 4; j++)
#pragma unroll
                for (int i = 0; i < 4; i++) acc[j][i] = 0.f;
        }
        __syncthreads();
    }
}

// ---------------- kernel 2: persistent HMMA score + softmax + V-agg ----------
__global__ __launch_bounds__(512, 1) void score_fused_kernel(
    const float* __restrict__ ea, const float* __restrict__ bE2v,
    float* __restrict__ out)
{
    extern __shared__ char smem[];
    const uint32_t sb = smem_u32(smem);
    const int tid = threadIdx.x, w = tid >> 5, lane = tid & 31;
    const int wm = w >> 1, wn = w & 1;
    const int g4 = lane >> 2, q = lane & 3;

    float4 pf[4];   // A refill LDG staging (one chunk)

    auto ldgChunk = [&](int baserow, int c) {
#pragma unroll
        for (int k = 0; k < 4; k++) {
            int i = tid + k * 512;
            int r = i >> 4, f4 = i & 15;
            pf[k] = *reinterpret_cast<const float4*>(
                ea + (size_t)(baserow + r) * 256 + c * 64 + f4 * 4);
        }
    };
    auto stsChunk = [&](int c) {
        char* ah = smem + OFF_A + (c * 2 + 0) * A_SPLIT_BYTES;
        char* al = smem + OFF_A + (c * 2 + 1) * A_SPLIT_BYTES;
#pragma unroll
        for (int k = 0; k < 4; k++) {
            int i = tid + k * 512;
            int r = i >> 4, f4 = i & 15;
            uint32_t hw0, lw0, hw1, lw1;
            split2(pf[k].x, pf[k].y, hw0, lw0);
            split2(pf[k].z, pf[k].w, hw1, lw1);
            uint32_t off = SWZ((uint32_t)(r * 128 + f4 * 8));
            *reinterpret_cast<uint2*>(ah + off) = make_uint2(hw0, hw1);
            *reinterpret_cast<uint2*>(al + off) = make_uint2(lw0, lw1);
        }
    };
    auto loadB = [&](int gc, int slot) {
        int g = gc >> 2, c = gc & 3;
        for (int v = tid; v < 1152; v += 512) {
            int s   = v / 576;
            int rem = v - s * 576;
            int r   = rem >> 3, u = rem & 7;
            int n   = (r < 64) ? (64 * g + r) : (256 + r - 64);
            const uint4* src = g_WB + (size_t)(s * 4 + c) * 2112 + n * 8 + u;
            uint32_t dst = sb + OFF_B + slot * B_BUF_BYTES + s * B_SPLIT_BYTES
                         + SWZ((uint32_t)(r * 128 + u * 16));
            cp_async16(dst, src);
        }
        CP_COMMIT();
    };

    int* nbr_base = reinterpret_cast<int*>(smem + OFF_NBR);
    float* ssc = reinterpret_cast<float*>(smem + OFF_SC);
    float* se2 = reinterpret_cast<float*>(smem + OFF_E2);
    float* sk  = reinterpret_cast<float*>(smem + OFF_SK) + wn * (128 * 33);
    float* sqp = reinterpret_cast<float*>(smem + OFF_SQ) + w * 32;

    const uint32_t a_off  = (uint32_t)((16 * wm + (lane & 15)) * 128 + (lane >> 4) * 16);
    const uint32_t bp_off = (uint32_t)(((lane & 7) + ((lane & 16) >> 1)) * 128
                                       + ((lane >> 3) & 1) * 16);
    const uint32_t b_off  = (uint32_t)((lane & 7) * 128 + ((lane >> 3) & 1) * 16);

    // -------- prologue: first tile --------
    int tile = blockIdx.x;
    if (tid < 128) nbr_base[tid] = g_nbr[tile * TILE_M + tid];
    loadB(0, 0);
#pragma unroll 1
    for (int cc = 0; cc < 4; cc++) { ldgChunk(tile * TILE_M, cc); stsChunk(cc); }

    float acc[5][4];
#pragma unroll
    for (int j = 0; j < 5; j++)
#pragma unroll
        for (int i = 0; i < 4; i++) acc[j][i] = 0.f;

    float kpf[16];
    float qpf = 0.f;

    int it = 0;
#pragma unroll 1
    for (; tile < N_TILES; tile += GRID_P, it++) {
        const bool has_next = (tile + GRID_P) < N_TILES;
        const int  nrow0 = (tile + GRID_P) * TILE_M;
        const int  node = tile * 4 + (wm >> 1);
        int* snbr  = nbr_base + (it & 1) * 128;
        int* snbrN = nbr_base + ((it + 1) & 1) * 128;

#pragma unroll 1
        for (int gc = 0; gc < 16; gc++) {
            const int g = gc >> 2, c = gc & 3, slot = gc & 1;
            __syncthreads();

            bool issued = false;
            if (gc < 15)       { loadB(gc + 1, (gc + 1) & 1); issued = true; }
            else if (has_next) { loadB(0, 0); issued = true; }
            if (issued) CP_WAIT1(); else CP_WAIT0();

            // A refill pipeline for next tile
            if (gc == 0 && it > 0) stsChunk(3);           // chunk3 of THIS tile
            if (has_next) {
                if (gc >= 13) stsChunk(gc - 13);          // chunks 0..2 of next
                if (gc >= 12) ldgChunk(nrow0, gc - 12);   // prefetch into pf
                if (gc == 13 && tid < 128) snbrN[tid] = g_nbr[nrow0 + tid];
            }

            // K/Q prefetch for this group's epilogue (used at c==3)
            if (c == 0) {
                int h = 2 * g + wn;
#pragma unroll
                for (int j = 0; j < 16; j++)
                    kpf[j] = g_K[(size_t)snbr[16 * wm + j] * 256 + h * 32 + lane];
                qpf = g_Q[(size_t)node * 256 + h * 32 + lane];
            }

            // ---- MMA: A chunk c x B(group g) ----
            {
                uint32_t Ah = sb + OFF_A + (c * 2 + 0) * A_SPLIT_BYTES;
                uint32_t Al = sb + OFF_A + (c * 2 + 1) * A_SPLIT_BYTES;
                uint32_t Bh = sb + OFF_B + slot * B_BUF_BYTES;
                uint32_t Bl = Bh + B_SPLIT_BYTES;
                bool do_e2 = (g == 3 && wn == 1);
#pragma unroll
                for (int ks = 0; ks < 4; ks++) {
                    uint32_t ao = SWZ(a_off + ks * 32);
                    uint32_t ahf[4], alf[4];
                    ldsm_x4(ahf, Ah + ao);
                    ldsm_x4(alf, Al + ao);
#pragma unroll
                    for (int jp = 0; jp < 2; jp++) {
                        uint32_t bo = SWZ((uint32_t)((32 * wn + 16 * jp) * 128)
                                          + bp_off + ks * 32);
                        uint32_t bh4[4], bl4[4];
                        ldsm_x4(bh4, Bh + bo);
                        ldsm_x4(bl4, Bl + bo);
                        mma16816(acc[2 * jp],     ahf, &bh4[0]);
                        mma16816(acc[2 * jp],     ahf, &bl4[0]);
                        mma16816(acc[2 * jp],     alf, &bh4[0]);
                        mma16816(acc[2 * jp + 1], ahf, &bh4[2]);
                        mma16816(acc[2 * jp + 1], ahf, &bl4[2]);
                        mma16816(acc[2 * jp + 1], alf, &bh4[2]);
                    }
                    if (do_e2) {
                        uint32_t bo = SWZ((uint32_t)(64 * 128) + b_off + ks * 32);
                        uint32_t bhf[2], blf[2];
                        ldsm_x2(bhf, Bh + bo);
                        ldsm_x2(blf, Bl + bo);
                        mma16816(acc[4], ahf, bhf);
                        mma16816(acc[4], ahf, blf);
                        mma16816(acc[4], alf, bhf);
                    }
                }
            }

            // ---- per-group epilogue ----
            if (c == 3) {
                const int h = 2 * g + wn;
#pragma unroll
                for (int j = 0; j < 16; j++)
                    sk[(16 * wm + j) * 33 + lane] = kpf[j];
                sqp[lane] = qpf;
                __syncwarp();

                float pg = 0.f, pg8 = 0.f;
                const float* skg  = sk + (16 * wm + g4) * 33;
                const float* skg8 = sk + (16 * wm + g4 + 8) * 33;
#pragma unroll
                for (int j2 = 0; j2 < 4; j2++) {
                    int c0 = j2 * 8 + 2 * q;
                    float q0 = sqp[c0], q1 = sqp[c0 + 1];
                    pg  += acc[j2][0] * skg[c0]  * q0 + acc[j2][1] * skg[c0 + 1]  * q1;
                    pg8 += acc[j2][2] * skg8[c0] * q0 + acc[j2][3] * skg8[c0 + 1] * q1;
                }
                pg  += __shfl_xor_sync(0xffffffffu, pg, 1);
                pg  += __shfl_xor_sync(0xffffffffu, pg, 2);
                pg8 += __shfl_xor_sync(0xffffffffu, pg8, 1);
                pg8 += __shfl_xor_sync(0xffffffffu, pg8, 2);
                if (q == 0) {
                    ssc[(16 * wm + g4) * 9 + h]     = pg;
                    ssc[(16 * wm + g4 + 8) * 9 + h] = pg8;
                }
                if (g == 3 && wn == 1) {
                    se2[(16 * wm + g4) * 9 + 2 * q]         = acc[4][0];
                    se2[(16 * wm + g4) * 9 + 2 * q + 1]     = acc[4][1];
                    se2[(16 * wm + g4 + 8) * 9 + 2 * q]     = acc[4][2];
                    se2[(16 * wm + g4 + 8) * 9 + 2 * q + 1] = acc[4][3];
                }
#pragma unroll
                for (int j = 0; j < 5; j++)
#pragma unroll
                    for (int i = 0; i < 4; i++) acc[j][i] = 0.f;
            }

            // ---- tile finalization at gc 15 ----
            if (gc == 15) {
                __syncthreads();
                for (int idx = tid; idx < 1024; idx += 512) {
                    int row = idx >> 3, h = idx & 7;
                    float s = ssc[row * 9 + h] + se2[row * 9 + h] + bE2v[h];
                    ssc[row * 9 + h] = fminf(fmaxf(s, -8.f), 8.f);
                }
                __syncthreads();

                float* att = reinterpret_cast<float*>(smem + OFF_ATT) + w * 32;
#pragma unroll
                for (int tix = 0; tix < 2; tix++) {
                    int t = w + tix * 16;
                    int nl = t >> 3, h = t & 7;
                    float s = ssc[(nl * 32 + lane) * 9 + h];
                    float m = s;
#pragma unroll
                    for (int off = 16; off; off >>= 1)
                        m = fmaxf(m, __shfl_xor_sync(0xffffffffu, m, off));
                    float ev = __expf(s - m);
                    float sum = ev;
#pragma unroll
                    for (int off = 16; off; off >>= 1)
                        sum += __shfl_xor_sync(0xffffffffu, sum, off);
                    att[lane] = ev / sum;
                    __syncwarp();

                    float a0 = 0.f, a1 = 0.f;
#pragma unroll 8
                    for (int dd = 0; dd < 32; dd += 2) {
                        a0 += att[dd]     * g_V[(size_t)snbr[nl * 32 + dd]     * 256 + h * 32 + lane];
                        a1 += att[dd + 1] * g_V[(size_t)snbr[nl * 32 + dd + 1] * 256 + h * 32 + lane];
                    }
                    out[(size_t)(tile * 4 + nl) * 256 + h * 32 + lane] = a0 + a1;
                    __syncwarp();
                }
            }
        }
    }
}

// ---------------- launch -----------------------------------------------------
extern "C" void kernel_launch(void* const* d_in, const int* in_sizes, int n_in,
                              void* d_out, int out_size)
{
    const float* x   = (const float*)d_in[0];
    const int*   ei  = (const int*)  d_in[1];
    const float* ea  = (const float*)d_in[2];
    const float* WQ  = (const float*)d_in[3];
    const float* WK  = (const float*)d_in[4];
    const float* WV  = (const float*)d_in[5];
    const float* WE1 = (const float*)d_in[6];
    const float* WE2 = (const float*)d_in[7];
    const float* bE2 = (const float*)d_in[8];
    float* out = (float*)d_out;

    cudaFuncSetAttribute(score_fused_kernel,
                         cudaFuncAttributeMaxDynamicSharedMemorySize, SMEM_TOTAL);
    cudaFuncSetAttribute(qkv_mma_kernel,
                         cudaFuncAttributeMaxDynamicSharedMemorySize, QSMEM_TOTAL);

    convert_idx_kernel<<<(N_EDGES + 255) / 256, 256>>>(ei);
    prep_wb_kernel<<<528, 256>>>(WE1, WE2);
    prep_wqkv_kernel<<<1536, 256>>>(WQ, WK, WV);

    qkv_mma_kernel<<<(N_NODES + QTILE_M - 1) / QTILE_M, 256, QSMEM_TOTAL>>>(x);

    score_fused_kernel<<<GRID_P, 512, SMEM_TOTAL>>>(ea, bE2, out);
}